// round 1
// baseline (speedup 1.0000x reference)
#include <cuda_runtime.h>
#include <math.h>

#define BATCH 256
#define S 64
#define M 64   // number of columns in the (possibly transposed) cost matrix: always 64

__device__ float g_loss[BATCH];

// One warp per batch element. Warp-synchronous Jonker-Volgenant (e-maxx) Hungarian
// with float64 duals (matches numpy reference bit-for-bit on the matching decisions),
// then the per-batch loss.
__global__ void __launch_bounds__(32) detr_match_loss_kernel(
    const float* __restrict__ pred_strokes,   // [B,S,10]
    const float* __restrict__ pred_validity,  // [B,S,1]
    const float* __restrict__ targets)        // [B,S,11]
{
    const int b = blockIdx.x;
    const int lane = threadIdx.x;

    __shared__ float ps[S * 10];
    __shared__ float gt[S * 10];
    __shared__ int   validIdx[S];
    __shared__ float C[S * M];
    __shared__ double u_[S + 1];
    __shared__ double v_[M + 1];
    __shared__ double minv[M + 1];
    __shared__ int    p_[M + 1];
    __shared__ int    way[M + 1];
    __shared__ int    used[M + 1];
    __shared__ int    sh_ng;

    const float* tgb = targets + (size_t)b * S * 11;
    const float* psb = pred_strokes + (size_t)b * S * 10;
    const float* pvb = pred_validity + (size_t)b * S;

    // Stage pred strokes into shared
    for (int idx = lane; idx < S * 10; idx += 32) ps[idx] = psb[idx];

    // BCE over all S slots (uses raw gt validity value, clip(log,.) at -100)
    float bce = 0.0f;
    for (int s = lane; s < S; s += 32) {
        float pv = pvb[s];
        float gv = tgb[s * 11 + 10];
        float lp  = fmaxf(logf(pv), -100.0f);
        float l1p = fmaxf(logf(1.0f - pv), -100.0f);
        bce += -(gv * lp + (1.0f - gv) * l1p);
    }
    #pragma unroll
    for (int o = 16; o; o >>= 1) bce += __shfl_xor_sync(0xffffffff, bce, o);
    bce *= (1.0f / 64.0f);

    // Compact valid target indices (serial on lane 0; only 64 items)
    if (lane == 0) {
        int ng = 0;
        for (int s = 0; s < S; s++)
            if (tgb[s * 11 + 10] > 0.5f) validIdx[ng++] = s;
        sh_ng = ng;
    }
    __syncwarp();
    const int n = sh_ng;

    if (n == 0) {
        if (lane == 0) g_loss[b] = bce;
        return;
    }

    // Stage compacted gt strokes
    for (int idx = lane; idx < n * 10; idx += 32) {
        int r = idx / 10, k = idx % 10;
        gt[idx] = tgb[validIdx[r] * 11 + k];
    }
    __syncwarp();

    // Orientation: reference transposes when rows(S=64) > cols(ng).
    // n = ng rows always, m = 64 cols always.
    const bool transposed = (n < 64);

    // Cost matrix C[i][j] (float32, matching numpy's pairwise-sum order, no FMA)
    for (int idx = lane; idx < n * M; idx += 32) {
        int i = idx >> 6, j = idx & 63;
        int pr = transposed ? j : i;   // pred row
        int gr = transposed ? i : j;   // gt (compacted) row
        const float* a = &ps[pr * 10];
        const float* g = &gt[gr * 10];
        float d0 = fabsf(a[0] - g[0]), d1 = fabsf(a[1] - g[1]);
        float d2 = fabsf(a[2] - g[2]), d3 = fabsf(a[3] - g[3]);
        float d4 = fabsf(a[4] - g[4]), d5 = fabsf(a[5] - g[5]);
        float d6 = fabsf(a[6] - g[6]), d7 = fabsf(a[7] - g[7]);
        float d8 = fabsf(a[8] - g[8]), d9 = fabsf(a[9] - g[9]);
        // numpy pairwise order for 8 elements:
        float sum8 = __fadd_rn(__fadd_rn(__fadd_rn(d0, d1), __fadd_rn(d2, d3)),
                               __fadd_rn(__fadd_rn(d4, d5), __fadd_rn(d6, d7)));
        float w2 = __fadd_rn(d8, d9);
        C[idx] = __fadd_rn(__fmul_rn(5.0f, sum8), w2);
    }

    // Init Hungarian state
    for (int j = lane; j <= M; j += 32) { p_[j] = 0; v_[j] = 0.0; way[j] = 0; }
    for (int r = lane; r <= n; r += 32) u_[r] = 0.0;
    __syncwarp();

    const double INF = 1e300;

    for (int i = 1; i <= n; i++) {
        for (int j = lane; j <= M; j += 32) { minv[j] = INF; used[j] = 0; }
        if (lane == 0) p_[0] = i;
        __syncwarp();

        int j0 = 0;
        while (true) {
            if (lane == 0) used[j0] = 1;
            __syncwarp();

            const int i0 = p_[j0];
            const double ui0 = u_[i0];

            double best = INF;
            int bestj = 0;
            const int ja = lane + 1;
            const int jb = lane + 33;

            if (!used[ja]) {
                double cur = (double)C[(i0 - 1) * M + (ja - 1)] - ui0 - v_[ja];
                if (cur < minv[ja]) { minv[ja] = cur; way[ja] = j0; }
                double mv = minv[ja];
                if (mv < best) { best = mv; bestj = ja; }
            }
            if (!used[jb]) {
                double cur = (double)C[(i0 - 1) * M + (jb - 1)] - ui0 - v_[jb];
                if (cur < minv[jb]) { minv[jb] = cur; way[jb] = j0; }
                double mv = minv[jb];
                if (mv < best) { best = mv; bestj = jb; }
            }
            // min-reduce (value, smallest index on tie) across warp
            #pragma unroll
            for (int o = 16; o; o >>= 1) {
                double ov = __shfl_xor_sync(0xffffffff, best, o);
                int    oj = __shfl_xor_sync(0xffffffff, bestj, o);
                if (ov < best || (ov == best && oj != 0 && oj < bestj)) { best = ov; bestj = oj; }
            }
            const double delta = best;
            const int j1 = bestj;

            // dual update (distinct rows among used columns -> no write conflicts)
            if (used[ja]) { u_[p_[ja]] += delta; v_[ja] -= delta; }
            else          { minv[ja]  -= delta; }
            if (used[jb]) { u_[p_[jb]] += delta; v_[jb] -= delta; }
            else          { minv[jb]  -= delta; }
            if (lane == 0) { u_[p_[0]] += delta; v_[0] -= delta; }
            __syncwarp();

            j0 = j1;
            if (p_[j0] == 0) break;
        }
        // augment along the alternating path
        if (lane == 0) {
            int jj = j0;
            while (jj) { int jprev = way[jj]; p_[jj] = p_[jprev]; jj = jprev; }
        }
        __syncwarp();
    }

    // Matched L1 loss over assigned (row,col) pairs
    float coord = 0.0f, width = 0.0f;
    for (int j = lane + 1; j <= M; j += 32) {
        int r = p_[j];
        if (r > 0) {
            int pr = transposed ? (j - 1) : (r - 1);
            int gr = transposed ? (r - 1) : (j - 1);
            const float* a = &ps[pr * 10];
            const float* g = &gt[gr * 10];
            #pragma unroll
            for (int k = 0; k < 8; k++) coord += fabsf(a[k] - g[k]);
            width += fabsf(a[8] - g[8]) + fabsf(a[9] - g[9]);
        }
    }
    #pragma unroll
    for (int o = 16; o; o >>= 1) {
        coord += __shfl_xor_sync(0xffffffff, coord, o);
        width += __shfl_xor_sync(0xffffffff, width, o);
    }

    if (lane == 0) {
        float ngf = (float)n;
        float loss = 5.0f * (coord / (ngf * 8.0f))
                   + 1.0f * (width / (ngf * 2.0f))
                   + 1.0f * bce;
        g_loss[b] = loss;
    }
}

// Deterministic tree reduction of per-batch losses -> scalar mean
__global__ void detr_reduce_kernel(float* __restrict__ out) {
    __shared__ float sh[BATCH];
    int t = threadIdx.x;
    sh[t] = g_loss[t];
    __syncthreads();
    #pragma unroll
    for (int o = BATCH / 2; o; o >>= 1) {
        if (t < o) sh[t] += sh[t + o];
        __syncthreads();
    }
    if (t == 0) out[0] = sh[0] * (1.0f / (float)BATCH);
}

extern "C" void kernel_launch(void* const* d_in, const int* in_sizes, int n_in,
                              void* d_out, int out_size) {
    const float* pred_strokes  = (const float*)d_in[0];
    const float* pred_validity = (const float*)d_in[1];
    const float* targets       = (const float*)d_in[2];
    float* out = (float*)d_out;

    detr_match_loss_kernel<<<BATCH, 32>>>(pred_strokes, pred_validity, targets);
    detr_reduce_kernel<<<1, BATCH>>>(out);
}

// round 2
// speedup vs baseline: 4.6769x; 4.6769x over previous
#include <cuda_runtime.h>
#include <math.h>

#define BATCH 256
#define S 64

__device__ float g_loss[BATCH];
__device__ unsigned int g_count;   // zero-initialized at module load; reset each run

// order-preserving float->uint key (handles tiny negative dists from fp rounding)
__device__ __forceinline__ unsigned okey(float f) {
    unsigned u = __float_as_uint(f);
    return u ^ (((unsigned)((int)u >> 31)) | 0x80000000u);
}

// One warp per batch. Warp-synchronous Jonker-Volgenant with greedy init.
// All per-column/per-row Dijkstra state lives in registers (2 slots per lane).
__global__ void __launch_bounds__(32) detr_fused_kernel(
    const float* __restrict__ pred_strokes,   // [B,S,10]
    const float* __restrict__ pred_validity,  // [B,S,1]
    const float* __restrict__ targets,        // [B,S,11]
    float* __restrict__ out)
{
    const int b = blockIdx.x;
    const int lane = threadIdx.x;
    const unsigned FULL = 0xffffffffu;
    const float INFV = __int_as_float(0x7f800000);

    __shared__ float ps[S * 10];
    __shared__ float gt[S * 10];
    __shared__ float C[S * 64];
    __shared__ float u_sh[S + 1];
    __shared__ int   validIdx[S];

    const float* tgb = targets + b * (S * 11);
    const float* psb = pred_strokes + b * (S * 10);
    const float* pvb = pred_validity + b * S;

    for (int idx = lane; idx < S * 10; idx += 32) ps[idx] = psb[idx];

    const float gv0 = tgb[lane * 11 + 10];
    const float gv1 = tgb[(lane + 32) * 11 + 10];

    // BCE over all 64 slots
    float pv0 = pvb[lane], pv1 = pvb[lane + 32];
    float bce = -(gv0 * fmaxf(logf(pv0), -100.f) + (1.f - gv0) * fmaxf(logf(1.f - pv0), -100.f))
                - (gv1 * fmaxf(logf(pv1), -100.f) + (1.f - gv1) * fmaxf(logf(1.f - pv1), -100.f));
    #pragma unroll
    for (int o = 16; o; o >>= 1) bce += __shfl_xor_sync(FULL, bce, o);
    bce *= (1.f / 64.f);

    // compact valid target indices (order-preserving, ballot+popc)
    unsigned m0 = __ballot_sync(FULL, gv0 > 0.5f);
    unsigned m1 = __ballot_sync(FULL, gv1 > 0.5f);
    int c0 = __popc(m0);
    int n  = c0 + __popc(m1);
    unsigned lt = (1u << lane) - 1u;
    if (gv0 > 0.5f) validIdx[__popc(m0 & lt)] = lane;
    if (gv1 > 0.5f) validIdx[c0 + __popc(m1 & lt)] = lane + 32;
    __syncwarp();

    float loss;
    if (n == 0) {
        loss = bce;
    } else {
        // stage compacted gt strokes
        for (int idx = lane; idx < n * 10; idx += 32) {
            int r = idx / 10, k = idx - r * 10;
            gt[idx] = tgb[validIdx[r] * 11 + k];
        }
        for (int idx = lane; idx <= S; idx += 32) u_sh[idx] = 0.f;
        __syncwarp();

        // orientation: reference transposes when S(64) > ng. rows=n, cols=64 always.
        const bool transposed = (n < 64);

        // cost matrix (float32, numpy pairwise-sum order, no FMA contraction)
        for (int idx = lane; idx < n * 64; idx += 32) {
            int i = idx >> 6, j = idx & 63;
            int pr = transposed ? j : i;
            int gr = transposed ? i : j;
            const float* a = &ps[pr * 10];
            const float* g = &gt[gr * 10];
            float d0 = fabsf(a[0] - g[0]), d1 = fabsf(a[1] - g[1]);
            float d2 = fabsf(a[2] - g[2]), d3 = fabsf(a[3] - g[3]);
            float d4 = fabsf(a[4] - g[4]), d5 = fabsf(a[5] - g[5]);
            float d6 = fabsf(a[6] - g[6]), d7 = fabsf(a[7] - g[7]);
            float d8 = fabsf(a[8] - g[8]), d9 = fabsf(a[9] - g[9]);
            float s8 = __fadd_rn(__fadd_rn(__fadd_rn(d0, d1), __fadd_rn(d2, d3)),
                                 __fadd_rn(__fadd_rn(d4, d5), __fadd_rn(d6, d7)));
            C[idx] = __fadd_rn(__fmul_rn(5.f, s8), __fadd_rn(d8, d9));
        }
        __syncwarp();

        const int jA = lane + 1, jB = lane + 33;  // columns owned by this lane
        float vA = 0.f, vB = 0.f;                  // column potentials
        int pA = 0, pB = 0;                        // row assigned to column (0 = free)

        // ---- JV init: row reduction + greedy tight-edge assignment ----
        for (int r = lane; r < n; r += 32) {
            const float* row = &C[r * 64];
            float mn = row[0];
            #pragma unroll 8
            for (int j = 1; j < 64; j++) mn = fminf(mn, row[j]);
            u_sh[r + 1] = mn;
        }
        __syncwarp();

        unsigned long long rowdone = 0ull;
        for (int i = 1; i <= n; i++) {
            float ui = u_sh[i];
            const float* Crow = &C[(i - 1) * 64];
            bool fA = (pA == 0) && (Crow[lane] == ui);
            bool fB = (pB == 0) && (Crow[lane + 32] == ui);
            unsigned bA = __ballot_sync(FULL, fA);
            unsigned bB = __ballot_sync(FULL, fB);
            int j1 = bA ? __ffs(bA) : (bB ? (__ffs(bB) + 32) : 0);
            if (j1) {
                if (lane == ((j1 - 1) & 31)) { if (j1 > 32) pB = i; else pA = i; }
                rowdone |= 1ull << (i - 1);
            }
        }

        // ---- shortest augmenting path phases for remaining rows ----
        for (int i = 1; i <= n; i++) {
            if ((rowdone >> (i - 1)) & 1ull) continue;

            float distA = INFV, distB = INFV;
            int wayA = 0, wayB = 0;
            bool usedA = false, usedB = false;
            float d0 = 0.f;
            int i0 = i, j0 = 0;

            while (true) {
                if (j0 == jA) usedA = true;
                if (j0 == jB) usedB = true;

                float base = d0 - u_sh[i0];
                const float* Crow = &C[(i0 - 1) * 64];
                if (!usedA) {
                    float cur = base + (Crow[lane] - vA);
                    if (cur < distA) { distA = cur; wayA = j0; }
                }
                if (!usedB) {
                    float cur = base + (Crow[lane + 32] - vB);
                    if (cur < distB) { distB = cur; wayB = j0; }
                }
                unsigned keyA = usedA ? 0xFFFFFFFFu : okey(distA);
                unsigned keyB = usedB ? 0xFFFFFFFFu : okey(distB);
                unsigned minkey = __reduce_min_sync(FULL, min(keyA, keyB));
                unsigned bA = __ballot_sync(FULL, keyA == minkey);
                unsigned bB = __ballot_sync(FULL, keyB == minkey);
                int j1 = bA ? __ffs(bA) : (__ffs(bB) + 32);
                int owner = (j1 - 1) & 31;
                d0 = __shfl_sync(FULL, (j1 > 32) ? distB : distA, owner);
                int pj1 = __shfl_sync(FULL, (j1 > 32) ? pB : pA, owner);
                j0 = j1;
                if (pj1 == 0) break;
                i0 = pj1;
            }

            // deferred potential updates: for used col j: adj = distF - dist[j]
            const float distF = d0;
            if (usedA) { float a = distF - distA; vA -= a; u_sh[pA] += a; }
            if (usedB) { float a = distF - distB; vB -= a; u_sh[pB] += a; }
            if (lane == 0) u_sh[i] += distF;   // virtual column 0 carries row i, dist 0
            __syncwarp();

            // augment along alternating path (j0 = free column)
            while (j0) {
                int o = (j0 - 1) & 31;
                int jprev = __shfl_sync(FULL, (j0 > 32) ? wayB : wayA, o);
                int jp = jprev > 0 ? jprev : 1;
                int pprev = __shfl_sync(FULL, (jp > 32) ? pB : pA, (jp - 1) & 31);
                if (jprev == 0) pprev = i;
                if (lane == o) { if (j0 > 32) pB = pprev; else pA = pprev; }
                j0 = jprev;
            }
        }

        // ---- matched L1 loss ----
        float coord = 0.f, width = 0.f;
        if (pA > 0) {
            int pr = transposed ? (jA - 1) : (pA - 1);
            int gr = transposed ? (pA - 1) : (jA - 1);
            const float* a = &ps[pr * 10];
            const float* g = &gt[gr * 10];
            #pragma unroll
            for (int k = 0; k < 8; k++) coord += fabsf(a[k] - g[k]);
            width += fabsf(a[8] - g[8]) + fabsf(a[9] - g[9]);
        }
        if (pB > 0) {
            int pr = transposed ? (jB - 1) : (pB - 1);
            int gr = transposed ? (pB - 1) : (jB - 1);
            const float* a = &ps[pr * 10];
            const float* g = &gt[gr * 10];
            #pragma unroll
            for (int k = 0; k < 8; k++) coord += fabsf(a[k] - g[k]);
            width += fabsf(a[8] - g[8]) + fabsf(a[9] - g[9]);
        }
        #pragma unroll
        for (int o = 16; o; o >>= 1) {
            coord += __shfl_xor_sync(FULL, coord, o);
            width += __shfl_xor_sync(FULL, width, o);
        }
        float ngf = (float)n;
        loss = 5.f * coord / (ngf * 8.f) + width / (ngf * 2.f) + bce;
    }

    // ---- fused final reduction: last block to finish reduces (fixed order -> deterministic) ----
    if (lane == 0) g_loss[b] = loss;
    __threadfence();
    unsigned ticket = 0;
    if (lane == 0) ticket = atomicAdd(&g_count, 1u);
    ticket = __shfl_sync(FULL, ticket, 0);
    if (ticket == BATCH - 1) {
        __threadfence();
        float s = 0.f;
        #pragma unroll
        for (int k = 0; k < BATCH / 32; k++) s += __ldcg(&g_loss[lane + 32 * k]);
        #pragma unroll
        for (int o = 16; o; o >>= 1) s += __shfl_xor_sync(FULL, s, o);
        if (lane == 0) {
            out[0] = s * (1.f / (float)BATCH);
            g_count = 0;   // reset for next graph replay
        }
    }
}

extern "C" void kernel_launch(void* const* d_in, const int* in_sizes, int n_in,
                              void* d_out, int out_size) {
    const float* pred_strokes  = (const float*)d_in[0];
    const float* pred_validity = (const float*)d_in[1];
    const float* targets       = (const float*)d_in[2];
    float* out = (float*)d_out;

    detr_fused_kernel<<<BATCH, 32>>>(pred_strokes, pred_validity, targets, out);
}

// round 3
// speedup vs baseline: 5.3774x; 1.1498x over previous
#include <cuda_runtime.h>
#include <math.h>

#define BATCH 256
#define S 64

__device__ float g_loss[BATCH];
__device__ unsigned int g_count;

// order-preserving float<->uint keys
__device__ __forceinline__ unsigned okey(float f) {
    unsigned u = __float_as_uint(f);
    return u ^ (((unsigned)((int)u >> 31)) | 0x80000000u);
}
__device__ __forceinline__ float dokey(unsigned k) {
    unsigned m = (((unsigned)((int)(~k) >> 31)) | 0x80000000u);
    return __uint_as_float(k ^ m);
}

// numpy pairwise-order cost, no FMA contraction
__device__ __forceinline__ float cost10(const float* a, const float* g) {
    float d0 = fabsf(a[0] - g[0]), d1 = fabsf(a[1] - g[1]);
    float d2 = fabsf(a[2] - g[2]), d3 = fabsf(a[3] - g[3]);
    float d4 = fabsf(a[4] - g[4]), d5 = fabsf(a[5] - g[5]);
    float d6 = fabsf(a[6] - g[6]), d7 = fabsf(a[7] - g[7]);
    float d8 = fabsf(a[8] - g[8]), d9 = fabsf(a[9] - g[9]);
    float s8 = __fadd_rn(__fadd_rn(__fadd_rn(d0, d1), __fadd_rn(d2, d3)),
                         __fadd_rn(__fadd_rn(d4, d5), __fadd_rn(d6, d7)));
    return __fadd_rn(__fmul_rn(5.f, s8), __fadd_rn(d8, d9));
}

__global__ void __launch_bounds__(32) detr_fused_kernel(
    const float* __restrict__ pred_strokes,   // [B,S,10]
    const float* __restrict__ pred_validity,  // [B,S,1]
    const float* __restrict__ targets,        // [B,S,11]
    float* __restrict__ out)
{
    const int b = blockIdx.x;
    const int lane = threadIdx.x;
    const unsigned FULL = 0xffffffffu;
    const float INFV = __int_as_float(0x7f800000);

    __shared__ float ps[S * 10];
    __shared__ float gt[S * 10];
    __shared__ float C[S * 64];
    __shared__ float u_sh[S + 1];
    __shared__ int   validIdx[S];

    const float* tgb = targets + b * (S * 11);
    const float* psb = pred_strokes + b * (S * 10);
    const float* pvb = pred_validity + b * S;

    for (int idx = lane; idx < S * 10; idx += 32) ps[idx] = psb[idx];

    const float gv0 = tgb[lane * 11 + 10];
    const float gv1 = tgb[(lane + 32) * 11 + 10];

    // BCE over all 64 slots
    float pv0 = pvb[lane], pv1 = pvb[lane + 32];
    float bce = -(gv0 * fmaxf(logf(pv0), -100.f) + (1.f - gv0) * fmaxf(logf(1.f - pv0), -100.f))
                - (gv1 * fmaxf(logf(pv1), -100.f) + (1.f - gv1) * fmaxf(logf(1.f - pv1), -100.f));
    #pragma unroll
    for (int o = 16; o; o >>= 1) bce += __shfl_xor_sync(FULL, bce, o);
    bce *= (1.f / 64.f);

    // compact valid target indices
    unsigned m0 = __ballot_sync(FULL, gv0 > 0.5f);
    unsigned m1 = __ballot_sync(FULL, gv1 > 0.5f);
    int c0 = __popc(m0);
    int n  = c0 + __popc(m1);
    unsigned lt = (1u << lane) - 1u;
    if (gv0 > 0.5f) validIdx[__popc(m0 & lt)] = lane;
    if (gv1 > 0.5f) validIdx[c0 + __popc(m1 & lt)] = lane + 32;
    __syncwarp();

    float loss;
    if (n == 0) {
        loss = bce;
    } else {
        // stage compacted gt strokes
        for (int idx = lane; idx < n * 10; idx += 32) {
            int r = idx / 10, k = idx - r * 10;
            gt[idx] = tgb[validIdx[r] * 11 + k];
        }
        __syncwarp();

        // orientation: transposed (rows=gt, cols=preds) whenever n < 64 (always in practice)
        const bool transposed = (n < 64);

        const int jA = lane + 1, jB = lane + 33;
        float vA = 0.f, vB = 0.f;
        int pA = 0, pB = 0;
        unsigned long long rowdone = 0ull;

        if (transposed) {
            // lane owns pred columns lane, lane+32: hoist strokes into registers
            float pa[10], pb[10];
            #pragma unroll
            for (int k = 0; k < 10; k++) {
                pa[k] = ps[lane * 10 + k];
                pb[k] = ps[(lane + 32) * 10 + k];
            }
            // fused: build C row + row-min + greedy tight-edge assignment
            for (int i = 0; i < n; i++) {
                float g[10];
                #pragma unroll
                for (int k = 0; k < 10; k++) g[k] = gt[i * 10 + k];  // broadcast
                float cA = cost10(pa, g);
                float cB = cost10(pb, g);
                C[i * 64 + lane] = cA;
                C[i * 64 + lane + 32] = cB;
                unsigned mk = __reduce_min_sync(FULL, min(okey(cA), okey(cB)));
                float ui = dokey(mk);
                if (lane == 0) u_sh[i + 1] = ui;
                bool fA = (pA == 0) && (cA == ui);
                bool fB = (pB == 0) && (cB == ui);
                unsigned bA = __ballot_sync(FULL, fA);
                unsigned bB = __ballot_sync(FULL, fB);
                int j1 = bA ? __ffs(bA) : (bB ? (__ffs(bB) + 32) : 0);
                if (j1) {
                    if (lane == ((j1 - 1) & 31)) { if (j1 > 32) pB = i + 1; else pA = i + 1; }
                    rowdone |= 1ull << i;
                }
            }
            __syncwarp();
        } else {
            // generic path (n == 64): rows=preds, cols=gt
            for (int idx = lane; idx < n * 64; idx += 32) {
                int i = idx >> 6, j = idx & 63;
                C[idx] = cost10(&ps[i * 10], &gt[j * 10]);
            }
            __syncwarp();
            for (int r = lane; r < n; r += 32) {
                const float* row = &C[r * 64];
                float mn = row[0];
                #pragma unroll 8
                for (int j = 1; j < 64; j++) mn = fminf(mn, row[j]);
                u_sh[r + 1] = mn;
            }
            __syncwarp();
            for (int i = 1; i <= n; i++) {
                float ui = u_sh[i];
                const float* Crow = &C[(i - 1) * 64];
                bool fA = (pA == 0) && (Crow[lane] == ui);
                bool fB = (pB == 0) && (Crow[lane + 32] == ui);
                unsigned bA = __ballot_sync(FULL, fA);
                unsigned bB = __ballot_sync(FULL, fB);
                int j1 = bA ? __ffs(bA) : (bB ? (__ffs(bB) + 32) : 0);
                if (j1) {
                    if (lane == ((j1 - 1) & 31)) { if (j1 > 32) pB = i; else pA = i; }
                    rowdone |= 1ull << (i - 1);
                }
            }
        }

        // ---- shortest augmenting path phases for remaining rows ----
        for (int i = 1; i <= n; i++) {
            if ((rowdone >> (i - 1)) & 1ull) continue;

            float distA = INFV, distB = INFV;
            int wayA = 0, wayB = 0;
            bool usedA = false, usedB = false;
            float d0 = 0.f;
            int i0 = i, j0 = 0;

            while (true) {
                if (j0 == jA) usedA = true;
                if (j0 == jB) usedB = true;

                float base = d0 - u_sh[i0];
                const float* Crow = &C[(i0 - 1) * 64];
                if (!usedA) {
                    float cur = base + (Crow[lane] - vA);
                    if (cur < distA) { distA = cur; wayA = j0; }
                }
                if (!usedB) {
                    float cur = base + (Crow[lane + 32] - vB);
                    if (cur < distB) { distB = cur; wayB = j0; }
                }
                unsigned keyA = usedA ? 0xFFFFFFFFu : okey(distA);
                unsigned keyB = usedB ? 0xFFFFFFFFu : okey(distB);
                unsigned minkey = __reduce_min_sync(FULL, min(keyA, keyB));
                d0 = dokey(minkey);               // exact winning dist, no shfl
                unsigned bA = __ballot_sync(FULL, keyA == minkey);
                unsigned bB = __ballot_sync(FULL, keyB == minkey);
                int j1, owner;
                if (bA) { owner = __ffs(bA) - 1; j1 = owner + 1;  }
                else    { owner = __ffs(bB) - 1; j1 = owner + 33; }
                int pj1 = __shfl_sync(FULL, (j1 > 32) ? pB : pA, owner);
                j0 = j1;
                if (pj1 == 0) break;
                i0 = pj1;
            }

            // deferred potential updates
            const float distF = d0;
            if (usedA) { float a = distF - distA; vA -= a; u_sh[pA] += a; }
            if (usedB) { float a = distF - distB; vB -= a; u_sh[pB] += a; }
            if (lane == 0) u_sh[i] += distF;
            __syncwarp();

            // augment along alternating path
            while (j0) {
                int o = (j0 - 1) & 31;
                int jprev = __shfl_sync(FULL, (j0 > 32) ? wayB : wayA, o);
                int jp = jprev > 0 ? jprev : 1;
                int pprev = __shfl_sync(FULL, (jp > 32) ? pB : pA, (jp - 1) & 31);
                if (jprev == 0) pprev = i;
                if (lane == o) { if (j0 > 32) pB = pprev; else pA = pprev; }
                j0 = jprev;
            }
        }

        // ---- matched L1 loss ----
        float coord = 0.f, width = 0.f;
        if (pA > 0) {
            int pr = transposed ? (jA - 1) : (pA - 1);
            int gr = transposed ? (pA - 1) : (jA - 1);
            const float* a = &ps[pr * 10];
            const float* g = &gt[gr * 10];
            #pragma unroll
            for (int k = 0; k < 8; k++) coord += fabsf(a[k] - g[k]);
            width += fabsf(a[8] - g[8]) + fabsf(a[9] - g[9]);
        }
        if (pB > 0) {
            int pr = transposed ? (jB - 1) : (pB - 1);
            int gr = transposed ? (pB - 1) : (jB - 1);
            const float* a = &ps[pr * 10];
            const float* g = &gt[gr * 10];
            #pragma unroll
            for (int k = 0; k < 8; k++) coord += fabsf(a[k] - g[k]);
            width += fabsf(a[8] - g[8]) + fabsf(a[9] - g[9]);
        }
        #pragma unroll
        for (int o = 16; o; o >>= 1) {
            coord += __shfl_xor_sync(FULL, coord, o);
            width += __shfl_xor_sync(FULL, width, o);
        }
        float ngf = (float)n;
        loss = 5.f * coord / (ngf * 8.f) + width / (ngf * 2.f) + bce;
    }

    // ---- fused final reduction (last warp reduces in fixed order -> deterministic) ----
    if (lane == 0) g_loss[b] = loss;
    __threadfence();
    unsigned ticket = 0;
    if (lane == 0) ticket = atomicAdd(&g_count, 1u);
    ticket = __shfl_sync(FULL, ticket, 0);
    if (ticket == BATCH - 1) {
        __threadfence();
        float s = 0.f;
        #pragma unroll
        for (int k = 0; k < BATCH / 32; k++) s += __ldcg(&g_loss[lane + 32 * k]);
        #pragma unroll
        for (int o = 16; o; o >>= 1) s += __shfl_xor_sync(FULL, s, o);
        if (lane == 0) {
            out[0] = s * (1.f / (float)BATCH);
            g_count = 0;
        }
    }
}

extern "C" void kernel_launch(void* const* d_in, const int* in_sizes, int n_in,
                              void* d_out, int out_size) {
    const float* pred_strokes  = (const float*)d_in[0];
    const float* pred_validity = (const float*)d_in[1];
    const float* targets       = (const float*)d_in[2];
    float* out = (float*)d_out;

    detr_fused_kernel<<<BATCH, 32>>>(pred_strokes, pred_validity, targets, out);
}

// round 5
// speedup vs baseline: 5.8163x; 1.0816x over previous
#include <cuda_runtime.h>
#include <math.h>

#define BATCH 256
#define S 64

__device__ float g_loss[BATCH];
__device__ unsigned int g_count;

// order-preserving float<->uint keys
__device__ __forceinline__ unsigned okey(float f) {
    unsigned u = __float_as_uint(f);
    return u ^ (((unsigned)((int)u >> 31)) | 0x80000000u);
}
__device__ __forceinline__ float dokey(unsigned k) {
    unsigned m = (((unsigned)((int)(~k) >> 31)) | 0x80000000u);
    return __uint_as_float(k ^ m);
}

// numpy pairwise-order cost, no FMA contraction
__device__ __forceinline__ float cost10(const float* a, const float* g) {
    float d0 = fabsf(a[0] - g[0]), d1 = fabsf(a[1] - g[1]);
    float d2 = fabsf(a[2] - g[2]), d3 = fabsf(a[3] - g[3]);
    float d4 = fabsf(a[4] - g[4]), d5 = fabsf(a[5] - g[5]);
    float d6 = fabsf(a[6] - g[6]), d7 = fabsf(a[7] - g[7]);
    float d8 = fabsf(a[8] - g[8]), d9 = fabsf(a[9] - g[9]);
    float s8 = __fadd_rn(__fadd_rn(__fadd_rn(d0, d1), __fadd_rn(d2, d3)),
                         __fadd_rn(__fadd_rn(d4, d5), __fadd_rn(d6, d7)));
    return __fadd_rn(__fmul_rn(5.f, s8), __fadd_rn(d8, d9));
}

__global__ void __launch_bounds__(64) detr_fused_kernel(
    const float* __restrict__ pred_strokes,   // [B,S,10]
    const float* __restrict__ pred_validity,  // [B,S,1]
    const float* __restrict__ targets,        // [B,S,11]
    float* __restrict__ out)
{
    const int b = blockIdx.x;
    const int tid = threadIdx.x;
    const int wid = tid >> 5;
    const int lane = tid & 31;
    const unsigned FULL = 0xffffffffu;
    const float INFV = __int_as_float(0x7f800000);

    __shared__ float ps[S * 10];
    __shared__ float gt[S * 10];
    __shared__ float C[S * 64];
    __shared__ float u_sh[S + 1];
    __shared__ int   validIdx[S];
    __shared__ float bce_sh;
    __shared__ int   n_sh;

    const float* tgb = targets + b * (S * 11);
    const float* psb = pred_strokes + b * (S * 10);
    const float* pvb = pred_validity + b * S;

    // cooperative ps staging
    for (int idx = tid; idx < S * 10; idx += 64) ps[idx] = psb[idx];

    if (wid == 0) {
        // compaction + gt staging
        float gv0 = tgb[lane * 11 + 10];
        float gv1 = tgb[(lane + 32) * 11 + 10];
        unsigned m0 = __ballot_sync(FULL, gv0 > 0.5f);
        unsigned m1 = __ballot_sync(FULL, gv1 > 0.5f);
        int c0 = __popc(m0);
        int nn = c0 + __popc(m1);
        unsigned lt = (1u << lane) - 1u;
        if (gv0 > 0.5f) validIdx[__popc(m0 & lt)] = lane;
        if (gv1 > 0.5f) validIdx[c0 + __popc(m1 & lt)] = lane + 32;
        if (lane == 0) n_sh = nn;
        __syncwarp();
        for (int idx = lane; idx < nn * 10; idx += 32) {
            int r = idx / 10, k = idx - r * 10;
            gt[idx] = tgb[validIdx[r] * 11 + k];
        }
    } else {
        // BCE over all 64 slots
        float gv0 = tgb[lane * 11 + 10];
        float gv1 = tgb[(lane + 32) * 11 + 10];
        float pv0 = pvb[lane], pv1 = pvb[lane + 32];
        float bce = -(gv0 * fmaxf(logf(pv0), -100.f) + (1.f - gv0) * fmaxf(logf(1.f - pv0), -100.f))
                    - (gv1 * fmaxf(logf(pv1), -100.f) + (1.f - gv1) * fmaxf(logf(1.f - pv1), -100.f));
        #pragma unroll
        for (int o = 16; o; o >>= 1) bce += __shfl_xor_sync(FULL, bce, o);
        if (lane == 0) bce_sh = bce * (1.f / 64.f);
    }
    __syncthreads();

    const int n = n_sh;
    const bool transposed = (n < 64);

    // ---- cost build: rows split across warps; per-row raw min -> u_sh (R3 values) ----
    if (n > 0) {
        if (transposed) {
            float pa[10], pb[10];
            #pragma unroll
            for (int k = 0; k < 10; k++) {
                pa[k] = ps[lane * 10 + k];
                pb[k] = ps[(lane + 32) * 10 + k];
            }
            int nh = n >> 1;
            int i0r = wid ? nh : 0;
            int i1r = wid ? n  : nh;
            for (int i = i0r; i < i1r; i++) {
                float g[10];
                #pragma unroll
                for (int k = 0; k < 10; k++) g[k] = gt[i * 10 + k];  // broadcast
                float cA = cost10(pa, g);
                float cB = cost10(pb, g);
                C[i * 64 + lane] = cA;
                C[i * 64 + lane + 32] = cB;
                unsigned mk = __reduce_min_sync(FULL, min(okey(cA), okey(cB)));
                if (lane == 0) u_sh[i + 1] = dokey(mk);
            }
        } else {
            // generic n==64 path: build split by tid
            for (int idx = tid; idx < 64 * 64; idx += 64) {
                int i = idx >> 6, j = idx & 63;
                C[idx] = cost10(&ps[i * 10], &gt[j * 10]);
            }
        }
    }
    __syncthreads();

    if (wid != 0) return;   // warp 1 done; warp 0 owns the sequential tail

    float loss;
    if (n == 0) {
        loss = bce_sh;
    } else {
        if (!transposed) {
            // row mins (warp 0 only; u_sh produced/consumed by warp 0)
            for (int r = lane; r < n; r += 32) {
                const float* row = &C[r * 64];
                float mn = row[0];
                #pragma unroll 8
                for (int j = 1; j < 64; j++) mn = fminf(mn, row[j]);
                u_sh[r + 1] = mn;
            }
            __syncwarp();
        }

        const int jA = lane + 1, jB = lane + 33;
        float vA = 0.f, vB = 0.f;
        int pA = 0, pB = 0;
        unsigned long long rowdone = 0ull;

        // ---- greedy tight-edge scan (raw costs vs raw row min, R3 semantics) ----
        for (int i = 0; i < n; i++) {
            float ui = u_sh[i + 1];
            float cA = C[i * 64 + lane];
            float cB = C[i * 64 + lane + 32];
            bool fA = (pA == 0) && (cA == ui);
            bool fB = (pB == 0) && (cB == ui);
            unsigned bA = __ballot_sync(FULL, fA);
            unsigned bB = __ballot_sync(FULL, fB);
            int j1 = bA ? __ffs(bA) : (bB ? (__ffs(bB) + 32) : 0);
            if (j1) {
                if (lane == ((j1 - 1) & 31)) { if (j1 > 32) pB = i + 1; else pA = i + 1; }
                rowdone |= 1ull << i;
            }
        }

        // ---- shortest augmenting path phases for remaining rows (R3 verbatim) ----
        for (int i = 1; i <= n; i++) {
            if ((rowdone >> (i - 1)) & 1ull) continue;

            float distA = INFV, distB = INFV;
            int wayA = 0, wayB = 0;
            bool usedA = false, usedB = false;
            float d0 = 0.f;
            int i0 = i, j0 = 0;

            while (true) {
                if (j0 == jA) usedA = true;
                if (j0 == jB) usedB = true;

                float base = d0 - u_sh[i0];
                const float* Crow = &C[(i0 - 1) * 64];
                if (!usedA) {
                    float cur = base + (Crow[lane] - vA);
                    if (cur < distA) { distA = cur; wayA = j0; }
                }
                if (!usedB) {
                    float cur = base + (Crow[lane + 32] - vB);
                    if (cur < distB) { distB = cur; wayB = j0; }
                }
                unsigned keyA = usedA ? 0xFFFFFFFFu : okey(distA);
                unsigned keyB = usedB ? 0xFFFFFFFFu : okey(distB);
                unsigned minkey = __reduce_min_sync(FULL, min(keyA, keyB));
                d0 = dokey(minkey);
                unsigned bA = __ballot_sync(FULL, keyA == minkey);
                unsigned bB = __ballot_sync(FULL, keyB == minkey);
                int j1, owner;
                if (bA) { owner = __ffs(bA) - 1; j1 = owner + 1;  }
                else    { owner = __ffs(bB) - 1; j1 = owner + 33; }
                int pj1 = __shfl_sync(FULL, (j1 > 32) ? pB : pA, owner);
                j0 = j1;
                if (pj1 == 0) break;
                i0 = pj1;
            }

            // deferred potential updates
            const float distF = d0;
            if (usedA) { float a = distF - distA; vA -= a; u_sh[pA] += a; }
            if (usedB) { float a = distF - distB; vB -= a; u_sh[pB] += a; }
            if (lane == 0) u_sh[i] += distF;
            __syncwarp();

            // augment along alternating path
            while (j0) {
                int o = (j0 - 1) & 31;
                int jprev = __shfl_sync(FULL, (j0 > 32) ? wayB : wayA, o);
                int jp = jprev > 0 ? jprev : 1;
                int pprev = __shfl_sync(FULL, (jp > 32) ? pB : pA, (jp - 1) & 31);
                if (jprev == 0) pprev = i;
                if (lane == o) { if (j0 > 32) pB = pprev; else pA = pprev; }
                j0 = jprev;
            }
        }

        // ---- matched L1 loss ----
        float coord = 0.f, width = 0.f;
        if (pA > 0) {
            int pr = transposed ? (jA - 1) : (pA - 1);
            int gr = transposed ? (pA - 1) : (jA - 1);
            const float* a = &ps[pr * 10];
            const float* g = &gt[gr * 10];
            #pragma unroll
            for (int k = 0; k < 8; k++) coord += fabsf(a[k] - g[k]);
            width += fabsf(a[8] - g[8]) + fabsf(a[9] - g[9]);
        }
        if (pB > 0) {
            int pr = transposed ? (jB - 1) : (pB - 1);
            int gr = transposed ? (pB - 1) : (jB - 1);
            const float* a = &ps[pr * 10];
            const float* g = &gt[gr * 10];
            #pragma unroll
            for (int k = 0; k < 8; k++) coord += fabsf(a[k] - g[k]);
            width += fabsf(a[8] - g[8]) + fabsf(a[9] - g[9]);
        }
        #pragma unroll
        for (int o = 16; o; o >>= 1) {
            coord += __shfl_xor_sync(FULL, coord, o);
            width += __shfl_xor_sync(FULL, width, o);
        }
        float ngf = (float)n;
        loss = 5.f * coord / (ngf * 8.f) + width / (ngf * 2.f) + bce_sh;
    }

    // ---- fused final reduction (last warp reduces in fixed order -> deterministic) ----
    if (lane == 0) g_loss[b] = loss;
    __threadfence();
    unsigned ticket = 0;
    if (lane == 0) ticket = atomicAdd(&g_count, 1u);
    ticket = __shfl_sync(FULL, ticket, 0);
    if (ticket == BATCH - 1) {
        __threadfence();
        float s = 0.f;
        #pragma unroll
        for (int k = 0; k < BATCH / 32; k++) s += __ldcg(&g_loss[lane + 32 * k]);
        #pragma unroll
        for (int o = 16; o; o >>= 1) s += __shfl_xor_sync(FULL, s, o);
        if (lane == 0) {
            out[0] = s * (1.f / (float)BATCH);
            g_count = 0;
        }
    }
}

extern "C" void kernel_launch(void* const* d_in, const int* in_sizes, int n_in,
                              void* d_out, int out_size) {
    const float* pred_strokes  = (const float*)d_in[0];
    const float* pred_validity = (const float*)d_in[1];
    const float* targets       = (const float*)d_in[2];
    float* out = (float*)d_out;

    detr_fused_kernel<<<BATCH, 64>>>(pred_strokes, pred_validity, targets, out);
}

// round 6
// speedup vs baseline: 6.3333x; 1.0889x over previous
#include <cuda_runtime.h>
#include <math.h>

#define BATCH 256
#define S 64

__device__ float g_loss[BATCH];
__device__ unsigned int g_count;

// order-preserving float<->uint keys
__device__ __forceinline__ unsigned okey(float f) {
    unsigned u = __float_as_uint(f);
    return u ^ (((unsigned)((int)u >> 31)) | 0x80000000u);
}
__device__ __forceinline__ float dokey(unsigned k) {
    unsigned m = (((unsigned)((int)(~k) >> 31)) | 0x80000000u);
    return __uint_as_float(k ^ m);
}

// numpy pairwise-order cost, no FMA contraction
__device__ __forceinline__ float cost10(const float* a, const float* g) {
    float d0 = fabsf(a[0] - g[0]), d1 = fabsf(a[1] - g[1]);
    float d2 = fabsf(a[2] - g[2]), d3 = fabsf(a[3] - g[3]);
    float d4 = fabsf(a[4] - g[4]), d5 = fabsf(a[5] - g[5]);
    float d6 = fabsf(a[6] - g[6]), d7 = fabsf(a[7] - g[7]);
    float d8 = fabsf(a[8] - g[8]), d9 = fabsf(a[9] - g[9]);
    float s8 = __fadd_rn(__fadd_rn(__fadd_rn(d0, d1), __fadd_rn(d2, d3)),
                         __fadd_rn(__fadd_rn(d4, d5), __fadd_rn(d6, d7)));
    return __fadd_rn(__fmul_rn(5.f, s8), __fadd_rn(d8, d9));
}

__global__ void __launch_bounds__(64) detr_fused_kernel(
    const float* __restrict__ pred_strokes,   // [B,S,10]
    const float* __restrict__ pred_validity,  // [B,S,1]
    const float* __restrict__ targets,        // [B,S,11]
    float* __restrict__ out)
{
    const int b = blockIdx.x;
    const int tid = threadIdx.x;
    const int wid = tid >> 5;
    const int lane = tid & 31;
    const unsigned FULL = 0xffffffffu;
    const float INFV = __int_as_float(0x7f800000);

    __shared__ float ps[S * 10];
    __shared__ float gt[S * 10];
    __shared__ float C[S * 64];
    __shared__ float u_sh[S + 1];
    __shared__ unsigned long long tight[S];
    __shared__ int   validIdx[S];
    __shared__ float bce_sh;
    __shared__ int   n_sh;

    const float* tgb = targets + b * (S * 11);
    const float* psb = pred_strokes + b * (S * 10);
    const float* pvb = pred_validity + b * S;

    // cooperative ps staging
    for (int idx = tid; idx < S * 10; idx += 64) ps[idx] = psb[idx];

    if (wid == 0) {
        // compaction + gt staging
        float gv0 = tgb[lane * 11 + 10];
        float gv1 = tgb[(lane + 32) * 11 + 10];
        unsigned m0 = __ballot_sync(FULL, gv0 > 0.5f);
        unsigned m1 = __ballot_sync(FULL, gv1 > 0.5f);
        int c0 = __popc(m0);
        int nn = c0 + __popc(m1);
        unsigned lt = (1u << lane) - 1u;
        if (gv0 > 0.5f) validIdx[__popc(m0 & lt)] = lane;
        if (gv1 > 0.5f) validIdx[c0 + __popc(m1 & lt)] = lane + 32;
        if (lane == 0) n_sh = nn;
        __syncwarp();
        for (int idx = lane; idx < nn * 10; idx += 32) {
            int r = idx / 10, k = idx - r * 10;
            gt[idx] = tgb[validIdx[r] * 11 + k];
        }
    } else {
        // BCE over all 64 slots
        float gv0 = tgb[lane * 11 + 10];
        float gv1 = tgb[(lane + 32) * 11 + 10];
        float pv0 = pvb[lane], pv1 = pvb[lane + 32];
        float bce = -(gv0 * fmaxf(logf(pv0), -100.f) + (1.f - gv0) * fmaxf(logf(1.f - pv0), -100.f))
                    - (gv1 * fmaxf(logf(pv1), -100.f) + (1.f - gv1) * fmaxf(logf(1.f - pv1), -100.f));
        #pragma unroll
        for (int o = 16; o; o >>= 1) bce += __shfl_xor_sync(FULL, bce, o);
        if (lane == 0) bce_sh = bce * (1.f / 64.f);
    }
    __syncthreads();

    const int n = n_sh;
    const bool transposed = (n < 64);

    // ---- cost build: rows split across warps; per-row raw min + tight-column mask ----
    if (n > 0) {
        if (transposed) {
            float pa[10], pb[10];
            #pragma unroll
            for (int k = 0; k < 10; k++) {
                pa[k] = ps[lane * 10 + k];
                pb[k] = ps[(lane + 32) * 10 + k];
            }
            int nh = n >> 1;
            int i0r = wid ? nh : 0;
            int i1r = wid ? n  : nh;
            for (int i = i0r; i < i1r; i++) {
                float g[10];
                #pragma unroll
                for (int k = 0; k < 10; k++) g[k] = gt[i * 10 + k];  // broadcast
                float cA = cost10(pa, g);
                float cB = cost10(pb, g);
                C[i * 64 + lane] = cA;
                C[i * 64 + lane + 32] = cB;
                unsigned mk = __reduce_min_sync(FULL, min(okey(cA), okey(cB)));
                float ui = dokey(mk);
                unsigned bA = __ballot_sync(FULL, cA == ui);
                unsigned bB = __ballot_sync(FULL, cB == ui);
                if (lane == 0) {
                    u_sh[i + 1] = ui;
                    tight[i] = (unsigned long long)bA | ((unsigned long long)bB << 32);
                }
            }
        } else {
            // generic n==64 path (statistically never taken): build split by tid
            for (int idx = tid; idx < 64 * 64; idx += 64) {
                int i = idx >> 6, j = idx & 63;
                C[idx] = cost10(&ps[i * 10], &gt[j * 10]);
            }
        }
    }
    __syncthreads();

    if (wid != 0) return;   // warp 1 done; warp 0 owns the sequential tail

    float loss;
    if (n == 0) {
        loss = bce_sh;
    } else {
        if (!transposed) {
            // generic path: row mins + tight masks (warp 0, per-row cooperative)
            for (int i = 0; i < n; i++) {
                float cA = C[i * 64 + lane];
                float cB = C[i * 64 + lane + 32];
                unsigned mk = __reduce_min_sync(FULL, min(okey(cA), okey(cB)));
                float ui = dokey(mk);
                unsigned bA = __ballot_sync(FULL, cA == ui);
                unsigned bB = __ballot_sync(FULL, cB == ui);
                if (lane == 0) {
                    u_sh[i + 1] = ui;
                    tight[i] = (unsigned long long)bA | ((unsigned long long)bB << 32);
                }
            }
            __syncwarp();
        }

        const int jA = lane + 1, jB = lane + 33;
        float vA = 0.f, vB = 0.f;
        int pA = 0, pB = 0;
        unsigned long long rowdone = 0ull;

        // ---- greedy tight-edge assignment (scalar bitmask scan, all lanes redundant) ----
        {
            unsigned long long freecols = ~0ull;
            for (int i = 0; i < n; i++) {
                unsigned long long t = tight[i] & freecols;
                if (t) {
                    int j = __ffsll((long long)t) - 1;   // column index 0..63
                    freecols &= ~(1ull << j);
                    rowdone |= 1ull << i;
                    if (j == lane) pA = i + 1;
                    if (j == lane + 32) pB = i + 1;
                }
            }
        }

        // ---- shortest augmenting path phases for remaining rows ----
        for (int i = 1; i <= n; i++) {
            if ((rowdone >> (i - 1)) & 1ull) continue;

            float distA = INFV, distB = INFV;
            int wayA = 0, wayB = 0;
            bool usedA = false, usedB = false;
            float d0 = 0.f;
            int i0 = i, j0 = 0;

            while (true) {
                if (j0 == jA) usedA = true;
                if (j0 == jB) usedB = true;

                float base = d0 - u_sh[i0];
                const float* Crow = &C[(i0 - 1) * 64];
                if (!usedA) {
                    float cur = base + (Crow[lane] - vA);
                    if (cur < distA) { distA = cur; wayA = j0; }
                }
                if (!usedB) {
                    float cur = base + (Crow[lane + 32] - vB);
                    if (cur < distB) { distB = cur; wayB = j0; }
                }
                // packed argmin: key's 6 LSBs carry the column index
                unsigned kA = usedA ? 0xFFFFFFFFu : okey(distA);
                unsigned kB = usedB ? 0xFFFFFFFFu : okey(distB);
                unsigned pkA = (kA & 0xFFFFFFC0u) | (unsigned)lane;
                unsigned pkB = (kB & 0xFFFFFFC0u) | (unsigned)(lane + 32);
                unsigned w = __reduce_min_sync(FULL, min(pkA, pkB));
                int col = (int)(w & 63u);          // 0..63
                int owner = col & 31;
                bool isB = col >= 32;
                // exact winning dist + its assigned row, fetched in parallel
                d0 = __shfl_sync(FULL, isB ? distB : distA, owner);
                int pj1 = __shfl_sync(FULL, isB ? pB : pA, owner);
                j0 = col + 1;
                if (pj1 == 0) break;
                i0 = pj1;
            }

            // deferred potential updates
            const float distF = d0;
            if (usedA) { float a = distF - distA; vA -= a; u_sh[pA] += a; }
            if (usedB) { float a = distF - distB; vB -= a; u_sh[pB] += a; }
            if (lane == 0) u_sh[i] += distF;
            __syncwarp();

            // augment along alternating path
            while (j0) {
                int o = (j0 - 1) & 31;
                int jprev = __shfl_sync(FULL, (j0 > 32) ? wayB : wayA, o);
                int jp = jprev > 0 ? jprev : 1;
                int pprev = __shfl_sync(FULL, (jp > 32) ? pB : pA, (jp - 1) & 31);
                if (jprev == 0) pprev = i;
                if (lane == o) { if (j0 > 32) pB = pprev; else pA = pprev; }
                j0 = jprev;
            }
        }

        // ---- matched L1 loss ----
        float coord = 0.f, width = 0.f;
        if (pA > 0) {
            int pr = transposed ? (jA - 1) : (pA - 1);
            int gr = transposed ? (pA - 1) : (jA - 1);
            const float* a = &ps[pr * 10];
            const float* g = &gt[gr * 10];
            #pragma unroll
            for (int k = 0; k < 8; k++) coord += fabsf(a[k] - g[k]);
            width += fabsf(a[8] - g[8]) + fabsf(a[9] - g[9]);
        }
        if (pB > 0) {
            int pr = transposed ? (jB - 1) : (pB - 1);
            int gr = transposed ? (pB - 1) : (jB - 1);
            const float* a = &ps[pr * 10];
            const float* g = &gt[gr * 10];
            #pragma unroll
            for (int k = 0; k < 8; k++) coord += fabsf(a[k] - g[k]);
            width += fabsf(a[8] - g[8]) + fabsf(a[9] - g[9]);
        }
        #pragma unroll
        for (int o = 16; o; o >>= 1) {
            coord += __shfl_xor_sync(FULL, coord, o);
            width += __shfl_xor_sync(FULL, width, o);
        }
        float ngf = (float)n;
        loss = 5.f * coord / (ngf * 8.f) + width / (ngf * 2.f) + bce_sh;
    }

    // ---- fused final reduction (last warp reduces in fixed order -> deterministic) ----
    if (lane == 0) g_loss[b] = loss;
    __threadfence();
    unsigned ticket = 0;
    if (lane == 0) ticket = atomicAdd(&g_count, 1u);
    ticket = __shfl_sync(FULL, ticket, 0);
    if (ticket == BATCH - 1) {
        __threadfence();
        float s = 0.f;
        #pragma unroll
        for (int k = 0; k < BATCH / 32; k++) s += __ldcg(&g_loss[lane + 32 * k]);
        #pragma unroll
        for (int o = 16; o; o >>= 1) s += __shfl_xor_sync(FULL, s, o);
        if (lane == 0) {
            out[0] = s * (1.f / (float)BATCH);
            g_count = 0;
        }
    }
}

extern "C" void kernel_launch(void* const* d_in, const int* in_sizes, int n_in,
                              void* d_out, int out_size) {
    const float* pred_strokes  = (const float*)d_in[0];
    const float* pred_validity = (const float*)d_in[1];
    const float* targets       = (const float*)d_in[2];
    float* out = (float*)d_out;

    detr_fused_kernel<<<BATCH, 64>>>(pred_strokes, pred_validity, targets, out);
}